// round 9
// baseline (speedup 1.0000x reference)
#include <cuda_runtime.h>
#include <cuda_bf16.h>
#include <math.h>
#include <stdint.h>

// ---------------------------------------------------------------------------
// PoincareEmbHingeLoss — HMMA bf16 GEMM + fused hinge epilogue
// (threshold + log-of-product), parallel prep, last-block finish.
// B=4096, C=10000 (padded 10112), D=64.
// ---------------------------------------------------------------------------

#define D_DIM 64
#define BM 128
#define BN 128
#define NT 256
#define MARGIN 0.1f
#define BOUNDARY_EPS 1e-5f
#define ACOSH_EPS 1e-7f
#define LN2F 0.69314718056f

#define MAX_B 4096
#define MAX_CP 10240
#define MAX_PARTIALS 4096

#define ROW_BYTES 144          // 64 bf16 = 128B, +16B pad -> conflict-free ldmatrix

__device__ __nv_bfloat16 g_pred_bf16[MAX_B * D_DIM];
__device__ __nv_bfloat16 g_all_bf16[MAX_CP * D_DIM];
__device__ float4 g_row_pack[MAX_B];    // {pn, 2/(1-pn), dm=d2c+margin, T=cosh(dm)-1}
__device__ float2 g_col_ania[MAX_CP];   // {an, 1/(1-an)}  (pad: {4e15, 1})
__device__ double g_partials[MAX_PARTIALS];
__device__ unsigned int g_done;

__device__ __forceinline__ uint32_t smem_u32(const void* p) {
    uint32_t a;
    asm("{ .reg .u64 t; cvta.to.shared.u64 t, %1; cvt.u32.u64 %0, t; }"
        : "=r"(a) : "l"(p));
    return a;
}

// ---------------------------------------------------------------------------
// Parallel prep: 8 threads per row/col; each sub handles 8 floats (2 float4),
// i.e. 4 bfloat162 outputs. Groups [0,B) = rows, [B,B+CP) = cols.
// ---------------------------------------------------------------------------
__global__ void prep_kernel(const float* __restrict__ pred,
                            const float* __restrict__ targ,
                            const float* __restrict__ all,
                            int B, int C, int CP) {
    if (blockIdx.x == 0 && threadIdx.x == 0) g_done = 0;  // reset for this launch

    int gtid = blockIdx.x * blockDim.x + threadIdx.x;
    int grp = gtid >> 3;          // one row/col per 8 threads
    int sub = gtid & 7;           // 0..7, each handles 8 floats (2 float4)

    if (grp < B) {
        // ---- row prep ----
        const float4* p4 = (const float4*)(pred + (size_t)grp * D_DIM) + sub * 2;
        const float4* t4 = (const float4*)(targ + (size_t)grp * D_DIM) + sub * 2;
        __nv_bfloat162* dst =
            (__nv_bfloat162*)(g_pred_bf16 + (size_t)grp * D_DIM) + sub * 4;
        float pn = 0.f, tn = 0.f, sc = 0.f;
#pragma unroll
        for (int i = 0; i < 2; i++) {
            float4 p = p4[i];
            float4 t = t4[i];
            pn += p.x * p.x + p.y * p.y + p.z * p.z + p.w * p.w;
            tn += t.x * t.x + t.y * t.y + t.z * t.z + t.w * t.w;
            float dx = p.x - t.x, dy = p.y - t.y, dz = p.z - t.z, dw = p.w - t.w;
            sc += dx * dx + dy * dy + dz * dz + dw * dw;
            dst[i * 2 + 0] = __floats2bfloat162_rn(p.x, p.y);
            dst[i * 2 + 1] = __floats2bfloat162_rn(p.z, p.w);
        }
        // butterfly over the 8-lane group
#pragma unroll
        for (int o = 4; o > 0; o >>= 1) {
            pn += __shfl_xor_sync(0xFFFFFFFFu, pn, o);
            tn += __shfl_xor_sync(0xFFFFFFFFu, tn, o);
            sc += __shfl_xor_sync(0xFFFFFFFFu, sc, o);
        }
        if (sub == 0) {
            pn = fminf(fmaxf(pn, 0.f), 1.f - BOUNDARY_EPS);
            tn = fminf(fmaxf(tn, 0.f), 1.f - BOUNDARY_EPS);
            double x = 1.0 + 2.0 * (double)sc /
                       ((1.0 - (double)pn) * (1.0 - (double)tn));
            double xm = 1.0 + (double)ACOSH_EPS;
            if (x < xm) x = xm;
            double d2c = log(x + sqrt(x * x - 1.0));
            double dm = d2c + (double)MARGIN;
            double T = cosh(dm) - 1.0;   // activity threshold on t
            g_row_pack[grp] = make_float4(pn, 2.f / (1.f - pn), (float)dm, (float)T);
        }
    } else if (grp < B + CP) {
        // ---- col prep ----
        int c = grp - B;
        __nv_bfloat162* dst =
            (__nv_bfloat162*)(g_all_bf16 + (size_t)c * D_DIM) + sub * 4;
        if (c < C) {
            const float4* a4 = (const float4*)(all + (size_t)c * D_DIM) + sub * 2;
            float an = 0.f;
#pragma unroll
            for (int i = 0; i < 2; i++) {
                float4 a = a4[i];
                an += a.x * a.x + a.y * a.y + a.z * a.z + a.w * a.w;
                dst[i * 2 + 0] = __floats2bfloat162_rn(a.x, a.y);
                dst[i * 2 + 1] = __floats2bfloat162_rn(a.z, a.w);
            }
#pragma unroll
            for (int o = 4; o > 0; o >>= 1)
                an += __shfl_xor_sync(0xFFFFFFFFu, an, o);
            if (sub == 0) {
                an = fminf(fmaxf(an, 0.f), 1.f - BOUNDARY_EPS);
                g_col_ania[c] = make_float2(an, 1.f / (1.f - an));
            }
        } else {
            __nv_bfloat162 z = __floats2bfloat162_rn(0.f, 0.f);
#pragma unroll
            for (int i = 0; i < 4; i++) dst[i] = z;
            if (sub == 0) g_col_ania[c] = make_float2(4e15f, 1.f);
        }
    }
}

// ---------------------------------------------------------------------------
// Fused HMMA GEMM tile (128x128, K=64) + threshold/log-product epilogue
// + last-block final reduction.
// ---------------------------------------------------------------------------
__global__ void __launch_bounds__(NT, 2)
fused_mma_kernel(float* __restrict__ out, int B, int C) {
    __shared__ char smA[BM * ROW_BYTES];     // 18432
    __shared__ char smB[BN * ROW_BYTES];     // 18432
    __shared__ float2 smAnia[BN];            // 1024
    __shared__ float4 smRow[BM];             // 2048
    __shared__ float smRed[8];
    __shared__ int smLast;

    const int tid = threadIdx.x;
    const int lane = tid & 31;
    const int wid = tid >> 5;
    const int m0 = blockIdx.y * BM;
    const int n0 = blockIdx.x * BN;
    const int nblocks = gridDim.x * gridDim.y;

    // ---- stage tiles ----
    const uint4* Ag = (const uint4*)(g_pred_bf16 + (size_t)m0 * D_DIM);
    const uint4* Bg = (const uint4*)(g_all_bf16 + (size_t)n0 * D_DIM);
#pragma unroll
    for (int i = 0; i < 4; i++) {
        int id = tid + i * NT;
        int r = id >> 3, c16 = id & 7;
        *(uint4*)(smA + r * ROW_BYTES + c16 * 16) = Ag[id];
        *(uint4*)(smB + r * ROW_BYTES + c16 * 16) = Bg[id];
    }
    if (tid < BN) smAnia[tid] = g_col_ania[n0 + tid];
    if (tid < BM) smRow[tid] = g_row_pack[m0 + tid];
    __syncthreads();

    const uint32_t sa = smem_u32(smA);
    const uint32_t sb = smem_u32(smB);
    const int wm = (wid & 3) * 32;      // warp row offset
    const int wn = (wid >> 2) * 64;     // warp col offset

    float acc[2][8][4];
#pragma unroll
    for (int mi = 0; mi < 2; mi++)
#pragma unroll
        for (int nj = 0; nj < 8; nj++)
#pragma unroll
            for (int e = 0; e < 4; e++) acc[mi][nj][e] = 0.f;

    const uint32_t a_lane_off = (uint32_t)((lane & 15) * ROW_BYTES + (lane >> 4) * 16);
    const int bmat = lane >> 3, brim = lane & 7;
    const uint32_t b_lane_off =
        (uint32_t)(((bmat & 1) * 8 + brim) * ROW_BYTES + (bmat >> 1) * 16);

#pragma unroll
    for (int ks = 0; ks < 4; ks++) {
        uint32_t af[2][4];
#pragma unroll
        for (int mi = 0; mi < 2; mi++) {
            uint32_t addr = sa + (uint32_t)((wm + mi * 16) * ROW_BYTES + ks * 32) + a_lane_off;
            asm volatile("ldmatrix.sync.aligned.m8n8.x4.shared.b16 {%0,%1,%2,%3}, [%4];"
                         : "=r"(af[mi][0]), "=r"(af[mi][1]), "=r"(af[mi][2]), "=r"(af[mi][3])
                         : "r"(addr));
        }
        uint32_t bfr[8][2];
#pragma unroll
        for (int g = 0; g < 4; g++) {
            uint32_t addr = sb + (uint32_t)((wn + g * 16) * ROW_BYTES + ks * 32) + b_lane_off;
            uint32_t r0, r1, r2, r3;
            asm volatile("ldmatrix.sync.aligned.m8n8.x4.shared.b16 {%0,%1,%2,%3}, [%4];"
                         : "=r"(r0), "=r"(r1), "=r"(r2), "=r"(r3)
                         : "r"(addr));
            bfr[2 * g + 0][0] = r0; bfr[2 * g + 0][1] = r2;
            bfr[2 * g + 1][0] = r1; bfr[2 * g + 1][1] = r3;
        }
#pragma unroll
        for (int mi = 0; mi < 2; mi++)
#pragma unroll
            for (int nj = 0; nj < 8; nj++)
                asm volatile(
                    "mma.sync.aligned.m16n8k16.row.col.f32.bf16.bf16.f32 "
                    "{%0,%1,%2,%3}, {%4,%5,%6,%7}, {%8,%9}, {%0,%1,%2,%3};"
                    : "+f"(acc[mi][nj][0]), "+f"(acc[mi][nj][1]),
                      "+f"(acc[mi][nj][2]), "+f"(acc[mi][nj][3])
                    : "r"(af[mi][0]), "r"(af[mi][1]), "r"(af[mi][2]), "r"(af[mi][3]),
                      "r"(bfr[nj][0]), "r"(bfr[nj][1]));
    }

    // ---- epilogue: threshold + log-of-product (1 sqrt/elem, 1 lg2 / 8 elems) ----
    const int gid = lane >> 2, tig = lane & 3;
    float4 rp[4];                     // [mi*2 + rowhalf]
    rp[0] = smRow[wm + gid];
    rp[1] = smRow[wm + gid + 8];
    rp[2] = smRow[wm + 16 + gid];
    rp[3] = smRow[wm + 16 + gid + 8];

    float cnt[4] = {0.f, 0.f, 0.f, 0.f};
    float logsum = 0.f;

#pragma unroll
    for (int njp = 0; njp < 4; njp++) {
        int c0 = wn + njp * 16 + tig * 2;
        float2 ca[4];
        ca[0] = smAnia[c0];
        ca[1] = smAnia[c0 + 1];
        ca[2] = smAnia[c0 + 8];
        ca[3] = smAnia[c0 + 9];
#pragma unroll
        for (int mi = 0; mi < 2; mi++) {
            float prod = 1.f;
#pragma unroll
            for (int jj = 0; jj < 2; jj++) {
#pragma unroll
                for (int e = 0; e < 4; e++) {
                    float acv = acc[mi][2 * njp + jj][e];
                    const float4& r = rp[mi * 2 + (e >> 1)];
                    const float2& c = ca[jj * 2 + (e & 1)];
                    float q = fmaf(-2.f, acv, r.x + c.x);
                    float t = fmaxf(q * (r.y * c.y), ACOSH_EPS);
                    bool act = t < r.w;                    // active iff t < cosh(dm)-1
                    float w = fmaf(t, t, t + t);           // t^2 + 2t
                    float s;
                    asm("sqrt.approx.f32 %0, %1;" : "=f"(s) : "f"(w));
                    float y = act ? (1.f + t + s) : 1.f;   // y = exp(dw) if active
                    prod *= y;
                    cnt[mi * 2 + (e >> 1)] += act ? 1.f : 0.f;
                }
            }
            float l;
            asm("lg2.approx.f32 %0, %1;" : "=f"(l) : "f"(prod));
            logsum += l;
        }
    }

    float tsum = fmaf(-LN2F, logsum, 0.f);
#pragma unroll
    for (int i = 0; i < 4; i++) tsum = fmaf(cnt[i], rp[i].z, tsum);

    // ---- warp-shuffle reduce, then cross-warp via smem ----
#pragma unroll
    for (int o = 16; o > 0; o >>= 1)
        tsum += __shfl_xor_sync(0xFFFFFFFFu, tsum, o);
    if (lane == 0) smRed[wid] = tsum;
    __syncthreads();
    if (tid == 0) {
        float s = 0.f;
#pragma unroll
        for (int i = 0; i < 8; i++) s += smRed[i];
        g_partials[blockIdx.y * gridDim.x + blockIdx.x] = (double)s;
        __threadfence();
        unsigned int v = atomicAdd(&g_done, 1u);
        smLast = (v == (unsigned int)(nblocks - 1)) ? 1 : 0;
    }
    __syncthreads();

    // ---- last block: deterministic final reduction (volatile reads) ----
    if (smLast) {
        volatile double* vp = g_partials;
        double* dred = (double*)smA;
        double s = 0.0;
        for (int i = tid; i < nblocks; i += NT) s += vp[i];
        dred[tid] = s;
        __syncthreads();
#pragma unroll
        for (int st = NT / 2; st > 0; st >>= 1) {
            if (tid < st) dred[tid] += dred[tid + st];
            __syncthreads();
        }
        if (tid == 0)
            out[0] = (float)((dred[0] - (double)MARGIN * (double)B) / (double)B);
    }
}

// ---------------------------------------------------------------------------
extern "C" void kernel_launch(void* const* d_in, const int* in_sizes, int n_in,
                              void* d_out, int out_size) {
    const float* pred = (const float*)d_in[0];
    const float* targ = (const float*)d_in[1];
    const float* all  = (const float*)d_in[2];
    float* out = (float*)d_out;

    int B = in_sizes[0] / D_DIM;               // 4096
    int C = in_sizes[2] / D_DIM;               // 10000
    int ctiles = (C + BN - 1) / BN;            // 79
    int CP = ctiles * BN;                      // 10112
    int rtiles = B / BM;                       // 32

    int nthreads = (B + CP) * 8;               // 8 threads per row/col
    prep_kernel<<<(nthreads + 255) / 256, 256>>>(pred, targ, all, B, C, CP);

    dim3 grid(ctiles, rtiles);                 // (79, 32) = 2528 tiles
    fused_mma_kernel<<<grid, NT>>>(out, B, C);
}